// round 11
// baseline (speedup 1.0000x reference)
#include <cuda_runtime.h>
#include <cstdint>
#include <cstddef>

// Problem constants
#define B_  32
#define P_  512
#define S_  1024
#define E_  512
#define H_  8
#define D_  64

// Scratch (allocation-free rule: __device__ globals)
__device__ float g_Q[(size_t)B_ * H_ * P_ * D_];   // (B,H,P,D)
__device__ float g_K[(size_t)B_ * H_ * S_ * D_];   // (B,H,S,D)
__device__ float g_V[(size_t)B_ * H_ * S_ * D_];   // (B,H,S,D)
__device__ float g_ctx[(size_t)B_ * P_ * E_];      // (B,P,E)

// ---------------- packed fp32 (f32x2) helpers: Blackwell sm_100+ ----------------
__device__ __forceinline__ void fma2(double &c, double a, double b) {
    asm("fma.rn.f32x2 %0, %1, %2, %0;" : "+d"(c) : "d"(a), "d"(b));
}
__device__ __forceinline__ void mul2(double &c, double a) {
    asm("mul.rn.f32x2 %0, %0, %1;" : "+d"(c) : "d"(a));
}
__device__ __forceinline__ double pack2(float x, float y) {
    double r; asm("mov.b64 %0, {%1, %2};" : "=d"(r) : "f"(x), "f"(y)); return r;
}
__device__ __forceinline__ float2 unpack2(double v) {
    float2 f; asm("mov.b64 {%0, %1}, %2;" : "=f"(f.x), "=f"(f.y) : "d"(v)); return f;
}

// ---------------- cp.async helpers ----------------
__device__ __forceinline__ void cp16(uint32_t dst_smem, const void* src_gmem) {
    asm volatile("cp.async.cg.shared.global [%0], [%1], 16;" :: "r"(dst_smem), "l"(src_gmem));
}
__device__ __forceinline__ void cp_commit() {
    asm volatile("cp.async.commit_group;");
}
template <int N>
__device__ __forceinline__ void cp_wait() {
    asm volatile("cp.async.wait_group %0;" :: "n"(N));
}

// =====================================================================
// GEMM body:  C[M,512] = A[M,512] @ W[512,512]^T   (+bias in mode 0)
// mode 0: plain row-major out, add bias
// mode 1: scatter out to (B, H, seq, D) layout:  m=(b,sq), n=(h,d)
//         seq is a power of two; seq_lg = log2(seq) -> shift/AND, no IDIV.
// m0 passed explicitly (callers may remap blockIdx for launch fusion).
// Tiles: BM=128, BN=64, BK=32; 256 threads; 8x4 C per thread;
// f32x2 pairing along K. 2-stage cp.async pipeline, ONE barrier per K-step:
//   { wait tile kt; bar; issue tile kt+1; compute tile kt }
// The post-barrier issue into stage (kt+1)&1 is ordered after all reads of
// that buffer (iteration kt-1's compute) because every thread passes this
// barrier only after finishing iteration kt-1.
// =====================================================================
#define GE_BM 128
#define GE_BN 64
#define GE_BK 32
#define GE_LDA 36                 // floats per row (32 + 4 pad -> 9 float4)
#define GE_AF  (GE_BM * GE_LDA)   // 4608 floats A-tile
#define GE_BF  (GE_BN * GE_LDA)   // 2304 floats B-tile
#define GE_STG (GE_AF + GE_BF)    // 6912 floats per stage
#define GE_SMEM_BYTES (2 * GE_STG * 4)   // 55296 B

__device__ __forceinline__
void gemm_body(float* smem, const float* __restrict__ A, const float* __restrict__ W,
               const float* __restrict__ bias, float* __restrict__ out,
               int m0, int seq_lg, int mode)
{
    const int tid = threadIdx.x;
    const int tx = tid & 15;        // 0..15  -> 4 strided cols (tx + 16j)
    const int ty = tid >> 4;        // 0..15  -> 8 contiguous rows (ty*8 + i)
    const int n0 = blockIdx.x * GE_BN;

    const float4* Ag = reinterpret_cast<const float4*>(A);
    const float4* Wg = reinterpret_cast<const float4*>(W);

    const uint32_t smem32 = (uint32_t)__cvta_generic_to_shared(smem);

    // per-thread load coordinates (fixed across K-steps)
    int a_row[4], a_kq[4], b_row[2], b_kq[2];
    #pragma unroll
    for (int c = 0; c < 4; c++) { int idx = tid + c * 256; a_row[c] = idx >> 3; a_kq[c] = idx & 7; }
    #pragma unroll
    for (int c = 0; c < 2; c++) { int idx = tid + c * 256; b_row[c] = idx >> 3; b_kq[c] = idx & 7; }

    // issue cp.async loads for K-tile kt into stage s
    auto issue_tile = [&](int kt, int s) {
        const int kq0 = kt * (GE_BK >> 2);
        const uint32_t baseA = smem32 + (uint32_t)(s * GE_STG) * 4u;
        const uint32_t baseB = baseA + (uint32_t)GE_AF * 4u;
        #pragma unroll
        for (int c = 0; c < 4; c++)
            cp16(baseA + (uint32_t)(a_row[c] * 9 + a_kq[c]) * 16u,
                 &Ag[(size_t)(m0 + a_row[c]) * 128 + kq0 + a_kq[c]]);
        #pragma unroll
        for (int c = 0; c < 2; c++)
            cp16(baseB + (uint32_t)(b_row[c] * 9 + b_kq[c]) * 16u,
                 &Wg[(size_t)(n0 + b_row[c]) * 128 + kq0 + b_kq[c]]);
        cp_commit();
    };

    double acc[8][4];
    #pragma unroll
    for (int i = 0; i < 8; i++)
        #pragma unroll
        for (int j = 0; j < 4; j++) acc[i][j] = 0.0;

    // ---- prologue: stage 0 in flight ----
    issue_tile(0, 0);

    const int NK = E_ / GE_BK;   // 16
    for (int kt = 0; kt < NK; kt++) {
        cp_wait<0>();            // tile kt landed (only group in flight)
        __syncthreads();         // visible to all; all readers of stage (kt+1)&1
                                 // from iteration kt-1 are done
        if (kt + 1 < NK) issue_tile(kt + 1, (kt + 1) & 1);

        const float* As = smem + (kt & 1) * GE_STG;
        const float* Bs = As + GE_AF;

        #pragma unroll
        for (int kk = 0; kk < 8; kk++) {
            double2 b[4];
            #pragma unroll
            for (int j = 0; j < 4; j++)
                b[j] = *reinterpret_cast<const double2*>(&Bs[(tx + 16 * j) * GE_LDA + kk * 4]);
            #pragma unroll
            for (int i = 0; i < 8; i++) {
                double2 a = *reinterpret_cast<const double2*>(&As[(ty * 8 + i) * GE_LDA + kk * 4]);
                #pragma unroll
                for (int j = 0; j < 4; j++) {
                    fma2(acc[i][j], a.x, b[j].x);
                    fma2(acc[i][j], a.y, b[j].y);
                }
            }
        }
        // no trailing barrier: next iteration's top __syncthreads orders
        // buffer reuse; last iteration needs nothing (no smem writes follow)
    }

    // Epilogue (seq power-of-two: shift/AND instead of IDIV)
    const int seq_mask = (1 << seq_lg) - 1;
    #pragma unroll
    for (int i = 0; i < 8; i++) {
        int m = m0 + ty * 8 + i;
        #pragma unroll
        for (int j = 0; j < 4; j++) {
            int n = n0 + tx + 16 * j;
            float2 f = unpack2(acc[i][j]);
            float v = f.x + f.y;
            if (mode == 0) {
                out[(size_t)m * E_ + n] = v + bias[n];
            } else {
                int bb = m >> seq_lg, sq = m & seq_mask;
                int hh = n >> 6, dd = n & 63;
                out[(((size_t)bb * H_ + hh) << seq_lg | sq) * D_ + dd] = v;
            }
        }
    }
}

// Output projection (mode 0) — standalone launch (depends on attention).
__global__ __launch_bounds__(256)
void gemm_nt_kernel(const float* __restrict__ A, const float* __restrict__ W,
                    const float* __restrict__ bias, float* __restrict__ out,
                    int seq_lg, int mode)
{
    extern __shared__ float smem[];
    gemm_body(smem, A, W, bias, out, blockIdx.y * GE_BM, seq_lg, mode);
}

// Q, K and V projections fused into ONE launch.
// grid = (8, 640): y in [0,128) -> Q rows, [128,384) -> K, [384,640) -> V.
// Dispatch is uniform per CTA (no divergence); all three use mode 1.
__global__ __launch_bounds__(256)
void gemm_qkv_kernel(const float* __restrict__ Qin, const float* __restrict__ Wq,
                     float* __restrict__ outQ,
                     const float* __restrict__ Kin, const float* __restrict__ Wk,
                     float* __restrict__ outK,
                     const float* __restrict__ Vin, const float* __restrict__ Wv,
                     float* __restrict__ outV)
{
    extern __shared__ float smem[];
    const int y = blockIdx.y;
    if (y < 128)
        gemm_body(smem, Qin, Wq, nullptr, outQ, y * GE_BM, 9, 1);
    else if (y < 384)
        gemm_body(smem, Kin, Wk, nullptr, outK, (y - 128) * GE_BM, 10, 1);
    else
        gemm_body(smem, Vin, Wv, nullptr, outV, (y - 384) * GE_BM, 10, 1);
}

// =====================================================================
// Fused masked attention, flash-style online softmax.
// Grid: (B*H, P/64). Block: 256 threads.
// Scores: f32x2 paired over d (Q,K natural layout).
// Ctx:    f32x2 paired over d (outer-product over s, V natural layout)
//         -> no V transpose; K/V double-buffered via cp.async.
// Q tile also loaded via cp.async in the same group as tile 0.
// Softmax running stats (m, l) in registers (row owned by the 16 lanes
// sharing ty; shfl reduction leaves the value in every lane).
// Ps rows are written AND read by the same half-warp -> mid-tile barrier is
// __syncwarp() only; cross-iteration reuse of Ps / K / V buffers is ordered
// by the top-of-iteration __syncthreads().
// Ctx phase reads Ps as float4 quads (16B-aligned: row stride 272B) and
// hoists 4 V d-pair loads per quad: 128 LDS per tile instead of 320.
// Thread map (scores):  tx=tid&15 -> s cols (tx+16j), ty=tid>>4 -> 4 p rows.
// Thread map (ctx):     tx -> d cols [tx*4, tx*4+4), same 4 p rows.
// =====================================================================
#define AT_LD 68               // 64 + 4 pad floats (17 float4, conflict-free)
#define AT_TF (64 * AT_LD)     // 4352 floats per tile
#define AT_SMEM_BYTES (6 * AT_TF * 4)   // 104448 B

__global__ __launch_bounds__(256)
void attn_kernel(const float* __restrict__ Q, const float* __restrict__ K,
                 const float* __restrict__ V, const int* __restrict__ mask,
                 float* __restrict__ ctx)
{
    extern __shared__ float sm[];
    float* Qs  = sm;                        // 64 x AT_LD
    float* Ks0 = sm + AT_TF;                // K stages (2)
    float* Vs0 = sm + 3 * AT_TF;            // V stages (2)
    float* Ps  = sm + 5 * AT_TF;            // probs 64 x AT_LD

    const int tid = threadIdx.x;
    const int tx = tid & 15;
    const int ty = tid >> 4;
    const int bh = blockIdx.x;
    const int b  = bh >> 3;
    const int h  = bh & 7;
    const int p0 = blockIdx.y * 64;
    const float scale = 0.125f;              // 64^-0.5

    const float4* Kg = reinterpret_cast<const float4*>(K + ((size_t)bh * S_) * D_);
    const float4* Vg = reinterpret_cast<const float4*>(V + ((size_t)bh * S_) * D_);
    const uint32_t smem32 = (uint32_t)__cvta_generic_to_shared(sm);

    // issue K+V tile st (64 x 64 each) into stage st&1 via cp.async
    auto issue_kv = [&](int st) {
        const int stg = st & 1;
        const uint32_t kb = smem32 + (uint32_t)((1 + stg) * AT_TF) * 4u;
        const uint32_t vb = smem32 + (uint32_t)((3 + stg) * AT_TF) * 4u;
        const float4* kg = Kg + (size_t)st * 64 * 16;
        const float4* vg = Vg + (size_t)st * 64 * 16;
        #pragma unroll
        for (int c = 0; c < 4; c++) {
            int idx = tid + c * 256;
            int s = idx >> 4, d4 = idx & 15;
            uint32_t off = (uint32_t)(s * AT_LD + d4 * 4) * 4u;
            cp16(kb + off, &kg[idx]);
            cp16(vb + off, &vg[idx]);
        }
        cp_commit();
    };

    // ---- prologue: Q tile + K/V tile 0 in one cp.async group ----
    {
        const float4* Qg = reinterpret_cast<const float4*>(Q + ((size_t)bh * P_ + p0) * D_);
        #pragma unroll
        for (int c = 0; c < 4; c++) {
            int idx = tid + c * 256;
            int p = idx >> 4, d4 = idx & 15;
            cp16(smem32 + (uint32_t)(p * AT_LD + d4 * 4) * 4u, &Qg[idx]);
        }
        // no separate commit: folded into issue_kv(0)'s group below
    }
    issue_kv(0);

    // running softmax stats in registers (per owned row i; same value in all
    // 16 lanes sharing ty after the shfl reductions)
    float m_run[4], l_run[4];
    #pragma unroll
    for (int i = 0; i < 4; i++) { m_run[i] = -1e30f; l_run[i] = 0.0f; }

    double acc[4][2];                        // ctx accumulators: 4 rows x 2 d-pairs
    #pragma unroll
    for (int i = 0; i < 4; i++) { acc[i][0] = 0.0; acc[i][1] = 0.0; }

    const int* mbase = mask + ((size_t)b * P_ + p0) * S_;

    for (int st = 0; st < 16; st++) {
        // mask bits for this tile (independent of smem; overlaps with cp.async)
        int mk[4][4];
        #pragma unroll
        for (int i = 0; i < 4; i++)
            #pragma unroll
            for (int j = 0; j < 4; j++)
                mk[i][j] = mbase[(size_t)(ty * 4 + i) * S_ + st * 64 + tx + 16 * j];

        cp_wait<0>();            // tile st (and, at st=0, the Q tile) landed
        __syncthreads();         // all readers of buffer st&1 from iter st-1 done;
                                 // also orders Ps reuse across iterations
        if (st + 1 < 16) issue_kv(st + 1);   // fill other buffer during compute

        const float* Kc = Ks0 + (st & 1) * AT_TF;
        const float* Vc = Vs0 + (st & 1) * AT_TF;

        // ---- scores: sacc[i][j] = sum_d Q[p][d]*K[s][d], f32x2 paired over d ----
        double sacc[4][4];
        #pragma unroll
        for (int i = 0; i < 4; i++)
            #pragma unroll
            for (int j = 0; j < 4; j++) sacc[i][j] = 0.0;

        #pragma unroll
        for (int d4 = 0; d4 < 16; d4++) {
            double2 bk[4];
            #pragma unroll
            for (int j = 0; j < 4; j++)
                bk[j] = *reinterpret_cast<const double2*>(&Kc[(tx + 16 * j) * AT_LD + d4 * 4]);
            #pragma unroll
            for (int i = 0; i < 4; i++) {
                double2 a = *reinterpret_cast<const double2*>(&Qs[(ty * 4 + i) * AT_LD + d4 * 4]);
                #pragma unroll
                for (int j = 0; j < 4; j++) {
                    fma2(sacc[i][j], a.x, bk[j].x);
                    fma2(sacc[i][j], a.y, bk[j].y);
                }
            }
        }

        // ---- reduce pairs, scale, mask ----
        float sc[4][4];
        #pragma unroll
        for (int i = 0; i < 4; i++)
            #pragma unroll
            for (int j = 0; j < 4; j++) {
                float2 f = unpack2(sacc[i][j]);
                float v = (f.x + f.y) * scale;
                sc[i][j] = mk[i][j] ? -1e30f : v;
            }

        // ---- online softmax per row (16-lane shfl; stats stay in regs) ----
        float corr[4];
        #pragma unroll
        for (int i = 0; i < 4; i++) {
            float mx = fmaxf(fmaxf(sc[i][0], sc[i][1]), fmaxf(sc[i][2], sc[i][3]));
            #pragma unroll
            for (int o = 8; o >= 1; o >>= 1)
                mx = fmaxf(mx, __shfl_xor_sync(0xffffffffu, mx, o, 16));
            float mn = fmaxf(m_run[i], mx);
            corr[i] = __expf(m_run[i] - mn);
            float rs = 0.0f;
            #pragma unroll
            for (int j = 0; j < 4; j++) {
                float e = __expf(sc[i][j] - mn);
                sc[i][j] = e;
                rs += e;
            }
            #pragma unroll
            for (int o = 8; o >= 1; o >>= 1)
                rs += __shfl_xor_sync(0xffffffffu, rs, o, 16);
            m_run[i] = mn;
            l_run[i] = l_run[i] * corr[i] + rs;
            #pragma unroll
            for (int j = 0; j < 4; j++)
                Ps[(ty * 4 + i) * AT_LD + tx + 16 * j] = sc[i][j];
        }
        // Ps rows (ty*4+i) are produced and consumed by the SAME half-warp;
        // no cross-warp dependency -> warp-level sync suffices here.
        __syncwarp(0xffffffffu);

        // ---- ctx update: outer product over s, f32x2 paired over d ----
        // thread owns d columns [tx*4, tx*4+4) for its 4 rows.
        // Quad-s granularity: 4 V d-pair loads + 4 float4 Ps loads per quad.
        #pragma unroll
        for (int i = 0; i < 4; i++) {
            double cc = pack2(corr[i], corr[i]);
            mul2(acc[i][0], cc);
            mul2(acc[i][1], cc);
        }
        #pragma unroll 4
        for (int s4 = 0; s4 < 16; s4++) {
            double2 vv[4];
            #pragma unroll
            for (int k = 0; k < 4; k++)
                vv[k] = *reinterpret_cast<const double2*>(&Vc[(s4 * 4 + k) * AT_LD + tx * 4]);
            #pragma unroll
            for (int i = 0; i < 4; i++) {
                float4 pv = *reinterpret_cast<const float4*>(&Ps[(ty * 4 + i) * AT_LD + s4 * 4]);
                double p0 = pack2(pv.x, pv.x);
                fma2(acc[i][0], p0, vv[0].x); fma2(acc[i][1], p0, vv[0].y);
                double p1 = pack2(pv.y, pv.y);
                fma2(acc[i][0], p1, vv[1].x); fma2(acc[i][1], p1, vv[1].y);
                double p2 = pack2(pv.z, pv.z);
                fma2(acc[i][0], p2, vv[2].x); fma2(acc[i][1], p2, vv[2].y);
                double p3 = pack2(pv.w, pv.w);
                fma2(acc[i][0], p3, vv[3].x); fma2(acc[i][1], p3, vv[3].y);
            }
        }
        // next iteration's top __syncthreads protects Ps and the K/V buffers
    }

    // ---- writeout: ctx (B,P,E), E index = h*64 + tx*4 .. +3 (float4) ----
    #pragma unroll
    for (int i = 0; i < 4; i++) {
        int row = ty * 4 + i;
        float inv = 1.0f / l_run[i];
        float2 a0 = unpack2(acc[i][0]);
        float2 a1 = unpack2(acc[i][1]);
        float4 o = make_float4(a0.x * inv, a0.y * inv, a1.x * inv, a1.y * inv);
        *reinterpret_cast<float4*>(
            &ctx[((size_t)b * P_ + p0 + row) * E_ + h * D_ + tx * 4]) = o;
    }
}

// =====================================================================
// launch
// =====================================================================
extern "C" void kernel_launch(void* const* d_in, const int* in_sizes, int n_in,
                              void* d_out, int out_size)
{
    const float* query = (const float*)d_in[0];
    const float* key   = (const float*)d_in[1];
    const float* value = (const float*)d_in[2];
    const int*   maskp = (const int*)  d_in[3];
    const float* Wq    = (const float*)d_in[4];
    const float* Wk    = (const float*)d_in[5];
    const float* Wv    = (const float*)d_in[6];
    const float* Wo    = (const float*)d_in[7];
    const float* bo    = (const float*)d_in[8];
    float* out = (float*)d_out;

    float *dQ, *dK, *dV, *dC;
    cudaGetSymbolAddress((void**)&dQ, g_Q);
    cudaGetSymbolAddress((void**)&dK, g_K);
    cudaGetSymbolAddress((void**)&dV, g_V);
    cudaGetSymbolAddress((void**)&dC, g_ctx);

    cudaFuncSetAttribute(attn_kernel, cudaFuncAttributeMaxDynamicSharedMemorySize, AT_SMEM_BYTES);
    cudaFuncSetAttribute(gemm_nt_kernel, cudaFuncAttributeMaxDynamicSharedMemorySize, GE_SMEM_BYTES);
    cudaFuncSetAttribute(gemm_qkv_kernel, cudaFuncAttributeMaxDynamicSharedMemorySize, GE_SMEM_BYTES);

    dim3 blk(256);
    // Q + K + V projections fused into ONE launch (y-range dispatch)
    gemm_qkv_kernel<<<dim3(E_ / GE_BN, 640), blk, GE_SMEM_BYTES>>>(
        query, Wq, dQ, key, Wk, dK, value, Wv, dV);
    // fused masked attention
    attn_kernel<<<dim3(B_ * H_, P_ / 64), blk, AT_SMEM_BYTES>>>(dQ, dK, dV, maskp, dC);
    // output projection + bias
    gemm_nt_kernel<<<dim3(E_ / GE_BN, (B_ * P_) / GE_BM), blk, GE_SMEM_BYTES>>>(dC, Wo, bo, out, 9, 0);
}

// round 16
// speedup vs baseline: 1.5462x; 1.5462x over previous
#include <cuda_runtime.h>
#include <cstdint>
#include <cstddef>

// Problem constants
#define B_  32
#define P_  512
#define S_  1024
#define E_  512
#define H_  8
#define D_  64

// Scratch (allocation-free rule: __device__ globals)
__device__ float g_Q[(size_t)B_ * H_ * P_ * D_];   // (B,H,P,D)
__device__ float g_K[(size_t)B_ * H_ * S_ * D_];   // (B,H,S,D)
__device__ float g_V[(size_t)B_ * H_ * S_ * D_];   // (B,H,S,D)
__device__ float g_ctx[(size_t)B_ * P_ * E_];      // (B,P,E)

// ---------------- packed fp32 (f32x2) helpers (attention kernel) ----------------
__device__ __forceinline__ void fma2(double &c, double a, double b) {
    asm("fma.rn.f32x2 %0, %1, %2, %0;" : "+d"(c) : "d"(a), "d"(b));
}
__device__ __forceinline__ void mul2(double &c, double a) {
    asm("mul.rn.f32x2 %0, %0, %1;" : "+d"(c) : "d"(a));
}
__device__ __forceinline__ double pack2(float x, float y) {
    double r; asm("mov.b64 %0, {%1, %2};" : "=d"(r) : "f"(x), "f"(y)); return r;
}
__device__ __forceinline__ float2 unpack2(double v) {
    float2 f; asm("mov.b64 {%0, %1}, %2;" : "=f"(f.x), "=f"(f.y) : "d"(v)); return f;
}

// ---------------- cp.async helpers ----------------
__device__ __forceinline__ void cp16(uint32_t dst_smem, const void* src_gmem) {
    asm volatile("cp.async.cg.shared.global [%0], [%1], 16;" :: "r"(dst_smem), "l"(src_gmem));
}
__device__ __forceinline__ void cp_commit() {
    asm volatile("cp.async.commit_group;");
}
template <int N>
__device__ __forceinline__ void cp_wait() {
    asm volatile("cp.async.wait_group %0;" :: "n"(N));
}

// ---------------- mma.sync (sm_80-class, legal on compute_103) ----------------
__device__ __forceinline__ void ldm_x4(uint32_t* r, uint32_t addr) {
    asm volatile("ldmatrix.sync.aligned.m8n8.x4.shared.b16 {%0,%1,%2,%3}, [%4];"
                 : "=r"(r[0]), "=r"(r[1]), "=r"(r[2]), "=r"(r[3]) : "r"(addr));
}
__device__ __forceinline__ void mma_bf16(float* d, const uint32_t* a, const uint32_t* b) {
    asm volatile(
        "mma.sync.aligned.m16n8k16.row.col.f32.bf16.bf16.f32 "
        "{%0,%1,%2,%3}, {%4,%5,%6,%7}, {%8,%9}, {%0,%1,%2,%3};"
        : "+f"(d[0]), "+f"(d[1]), "+f"(d[2]), "+f"(d[3])
        : "r"(a[0]), "r"(a[1]), "r"(a[2]), "r"(a[3]), "r"(b[0]), "r"(b[1]));
}

// bf16x2 pack / unpack
__device__ __forceinline__ uint32_t bf2(float lo, float hi) {
    uint32_t r; asm("cvt.rn.bf16x2.f32 %0, %1, %2;" : "=r"(r) : "f"(hi), "f"(lo)); return r;
}
__device__ __forceinline__ float2 bf2f(uint32_t p) {
    return make_float2(__uint_as_float(p << 16), __uint_as_float(p & 0xffff0000u));
}

// =====================================================================
// Tensor-core split-precision GEMM via mma.sync (HMMA path):
//   C[M,512] = A[M,512] @ W[512,512]^T   (+bias in mode 0)
// bf16x3: x = hi + lo; products hi*hi + hi*lo + lo*hi in fp32 accums
// (lo*lo ~2^-18 relative, dropped). Predicted rel_err ~1e-4.
// Per CTA: 128x128 tile, 8 warps as 4(m) x 2(n): warp = 32 rows x 64 cols
// = 2 m-tiles(16) x 8 n-tiles(8) of m16n8k16. K in 8 chunks of 64.
// Smem: Ah/Al/Bh/Bl tiles, 128 rows x 64 bf16, row stride 144B
// (36 words: ldmatrix 8-row groups hit disjoint 4-bank spans -> conflict-free).
// Per chunk: all threads convert/split fp32->bf16 (LDG float4 -> STS uint2);
// bar; 4 k-steps x { ldmatrix Ah,Bh; mma hh; ldmatrix Bl; mma h*l;
// ldmatrix Al; mma l*h }. Cross-CTA overlap (2 CTAs/SM) hides the LDG phase.
// Epilogue from register accumulators (m16n8 lane map: row=lane>>2 (+8),
// cols=2*(lane&3)).
// mode 0: row-major + bias; mode 1: scatter to (B,H,seq,D), seq=1<<seq_lg.
// =====================================================================
#define MM_LDB  144                       // bytes per smem row (64 bf16 + pad)
#define MM_TILE (128 * MM_LDB)            // 18432 B per tile
#define MM_AH   0
#define MM_AL   (MM_TILE)
#define MM_BH   (2 * MM_TILE)
#define MM_BL   (3 * MM_TILE)
#define MM_SMEM (4 * MM_TILE)             // 73728 B

__device__ __forceinline__
void split_store2(char* smem, int baseH, int baseL, uint32_t off, float4 v) {
    uint32_t h0 = bf2(v.x, v.y); float2 f0 = bf2f(h0);
    uint32_t h1 = bf2(v.z, v.w); float2 f1 = bf2f(h1);
    uint32_t l0 = bf2(v.x - f0.x, v.y - f0.y);
    uint32_t l1 = bf2(v.z - f1.x, v.w - f1.y);
    *reinterpret_cast<uint2*>(smem + baseH + off) = make_uint2(h0, h1);
    *reinterpret_cast<uint2*>(smem + baseL + off) = make_uint2(l0, l1);
}

__device__ __forceinline__
void mm_gemm_body(char* smem, const float* __restrict__ A, const float* __restrict__ W,
                  const float* __restrict__ bias, float* __restrict__ out,
                  int m0, int seq_lg, int mode)
{
    const int tid    = threadIdx.x;
    const int lane   = tid & 31;
    const int wid    = tid >> 5;
    const int warp_m = wid & 3;           // 4 warps over M (32 rows each)
    const int warp_n = wid >> 2;          // 2 warps over N (64 cols each)
    const int n0 = blockIdx.x * 128;
    const uint32_t smem32 = (uint32_t)__cvta_generic_to_shared(smem);

    const float4* Ag = reinterpret_cast<const float4*>(A);
    const float4* Wg = reinterpret_cast<const float4*>(W);

    float d[2][8][4];
    #pragma unroll
    for (int mt = 0; mt < 2; mt++)
        #pragma unroll
        for (int nt = 0; nt < 8; nt++)
            #pragma unroll
            for (int r = 0; r < 4; r++) d[mt][nt][r] = 0.0f;

    // ldmatrix lane-address components (fixed per thread)
    // A frag (x4): row = base + (lane&15), col-half = lane>>4
    const int a_row_off = lane & 15;
    const int a_col_off = (lane >> 4) * 16;          // bytes
    // B frag pair (x4): row = base + ((lane>>4)<<3) + (lane&7), k-half = (lane>>3)&1
    const int b_row_off = ((lane >> 4) << 3) + (lane & 7);
    const int b_col_off = ((lane >> 3) & 1) * 16;    // bytes

    for (int chunk = 0; chunk < 8; chunk++) {
        __syncthreads();   // prior chunk's ldmatrix reads complete before overwrite

        // ---- convert/split A chunk (128 rows x 64 cols) ----
        #pragma unroll
        for (int c = 0; c < 8; c++) {
            int idx = tid + c * 256;
            int row = idx >> 4, f4 = idx & 15;
            float4 v = Ag[(size_t)(m0 + row) * 128 + chunk * 16 + f4];
            split_store2(smem, MM_AH, MM_AL, (uint32_t)(row * MM_LDB + f4 * 8), v);
        }
        // ---- convert/split B chunk (128 rows x 64 cols) ----
        #pragma unroll
        for (int c = 0; c < 8; c++) {
            int idx = tid + c * 256;
            int row = idx >> 4, f4 = idx & 15;
            float4 v = Wg[(size_t)(n0 + row) * 128 + chunk * 16 + f4];
            split_store2(smem, MM_BH, MM_BL, (uint32_t)(row * MM_LDB + f4 * 8), v);
        }
        __syncthreads();

        // ---- compute: 4 k-steps of K=16 ----
        #pragma unroll
        for (int ks = 0; ks < 4; ks++) {
            const int kb = ks * 32;   // byte offset of this k-step (16 bf16)

            uint32_t ah[2][4];
            #pragma unroll
            for (int mt = 0; mt < 2; mt++)
                ldm_x4(ah[mt], smem32 + MM_AH +
                       (uint32_t)((warp_m * 32 + mt * 16 + a_row_off) * MM_LDB + a_col_off + kb));

            uint32_t bh[4][4];
            #pragma unroll
            for (int p = 0; p < 4; p++)
                ldm_x4(bh[p], smem32 + MM_BH +
                       (uint32_t)((warp_n * 64 + p * 16 + b_row_off) * MM_LDB + b_col_off + kb));

            // hi * hi
            #pragma unroll
            for (int mt = 0; mt < 2; mt++)
                #pragma unroll
                for (int nt = 0; nt < 8; nt++)
                    mma_bf16(d[mt][nt], ah[mt], &bh[nt >> 1][(nt & 1) * 2]);

            // hi * lo
            {
                uint32_t bl[4][4];
                #pragma unroll
                for (int p = 0; p < 4; p++)
                    ldm_x4(bl[p], smem32 + MM_BL +
                           (uint32_t)((warp_n * 64 + p * 16 + b_row_off) * MM_LDB + b_col_off + kb));
                #pragma unroll
                for (int mt = 0; mt < 2; mt++)
                    #pragma unroll
                    for (int nt = 0; nt < 8; nt++)
                        mma_bf16(d[mt][nt], ah[mt], &bl[nt >> 1][(nt & 1) * 2]);
            }

            // lo * hi
            {
                uint32_t al[2][4];
                #pragma unroll
                for (int mt = 0; mt < 2; mt++)
                    ldm_x4(al[mt], smem32 + MM_AL +
                           (uint32_t)((warp_m * 32 + mt * 16 + a_row_off) * MM_LDB + a_col_off + kb));
                #pragma unroll
                for (int mt = 0; mt < 2; mt++)
                    #pragma unroll
                    for (int nt = 0; nt < 8; nt++)
                        mma_bf16(d[mt][nt], al[mt], &bh[nt >> 1][(nt & 1) * 2]);
            }
            // lo*lo dropped: ~2^-18 relative, below fp32 output rounding
        }
    }

    // ---- epilogue from register accumulators ----
    const int gid = lane >> 2, tig = lane & 3;
    const int seq_mask = (1 << seq_lg) - 1;
    #pragma unroll
    for (int mt = 0; mt < 2; mt++) {
        #pragma unroll
        for (int half = 0; half < 2; half++) {
            int m = m0 + warp_m * 32 + mt * 16 + gid + half * 8;
            #pragma unroll
            for (int nt = 0; nt < 8; nt++) {
                int n = n0 + warp_n * 64 + nt * 8 + tig * 2;
                float2 v = make_float2(d[mt][nt][half * 2], d[mt][nt][half * 2 + 1]);
                if (mode == 0) {
                    v.x += bias[n]; v.y += bias[n + 1];
                    *reinterpret_cast<float2*>(&out[(size_t)m * E_ + n]) = v;
                } else {
                    int bb = m >> seq_lg, sq = m & seq_mask;
                    int hh = n >> 6, dd = n & 63;
                    *reinterpret_cast<float2*>(
                        &out[(size_t)(((bb * H_ + hh) << seq_lg) | sq) * 64 + dd]) = v;
                }
            }
        }
    }
}

// Q, K, V projections fused in one launch: grid (4, 640); y-range dispatch.
__global__ __launch_bounds__(256, 2)
void mm_qkv_kernel(const float* __restrict__ Qin, const float* __restrict__ Wq, float* __restrict__ outQ,
                   const float* __restrict__ Kin, const float* __restrict__ Wk, float* __restrict__ outK,
                   const float* __restrict__ Vin, const float* __restrict__ Wv, float* __restrict__ outV)
{
    extern __shared__ char mmsm[];
    const int y = blockIdx.y;
    if (y < 128)      mm_gemm_body(mmsm, Qin, Wq, nullptr, outQ, y * 128, 9, 1);
    else if (y < 384) mm_gemm_body(mmsm, Kin, Wk, nullptr, outK, (y - 128) * 128, 10, 1);
    else              mm_gemm_body(mmsm, Vin, Wv, nullptr, outV, (y - 384) * 128, 10, 1);
}

// Output projection + bias: grid (4, 128)
__global__ __launch_bounds__(256, 2)
void mm_out_kernel(const float* __restrict__ A, const float* __restrict__ Wo,
                   const float* __restrict__ bo, float* __restrict__ out)
{
    extern __shared__ char mmsm2[];
    mm_gemm_body(mmsm2, A, Wo, bo, out, blockIdx.y * 128, 9, 0);
}

// =====================================================================
// Fused masked attention (unchanged from the 1954us-passing version).
// =====================================================================
#define AT_LD 68               // 64 + 4 pad floats (17 float4, conflict-free)
#define AT_TF (64 * AT_LD)     // 4352 floats per tile
#define AT_SMEM_BYTES (6 * AT_TF * 4)   // 104448 B

__global__ __launch_bounds__(256)
void attn_kernel(const float* __restrict__ Q, const float* __restrict__ K,
                 const float* __restrict__ V, const int* __restrict__ mask,
                 float* __restrict__ ctx)
{
    extern __shared__ float sm[];
    float* Qs  = sm;                        // 64 x AT_LD
    float* Ks0 = sm + AT_TF;                // K stages (2)
    float* Vs0 = sm + 3 * AT_TF;            // V stages (2)
    float* Ps  = sm + 5 * AT_TF;            // probs 64 x AT_LD

    const int tid = threadIdx.x;
    const int tx = tid & 15;
    const int ty = tid >> 4;
    const int bh = blockIdx.x;
    const int b  = bh >> 3;
    const int h  = bh & 7;
    const int p0 = blockIdx.y * 64;
    const float scale = 0.125f;              // 64^-0.5

    const float4* Kg = reinterpret_cast<const float4*>(K + ((size_t)bh * S_) * D_);
    const float4* Vg = reinterpret_cast<const float4*>(V + ((size_t)bh * S_) * D_);
    const uint32_t smem32 = (uint32_t)__cvta_generic_to_shared(sm);

    auto issue_kv = [&](int st) {
        const int stg = st & 1;
        const uint32_t kb = smem32 + (uint32_t)((1 + stg) * AT_TF) * 4u;
        const uint32_t vb = smem32 + (uint32_t)((3 + stg) * AT_TF) * 4u;
        const float4* kg = Kg + (size_t)st * 64 * 16;
        const float4* vg = Vg + (size_t)st * 64 * 16;
        #pragma unroll
        for (int c = 0; c < 4; c++) {
            int idx = tid + c * 256;
            int s = idx >> 4, d4 = idx & 15;
            uint32_t off = (uint32_t)(s * AT_LD + d4 * 4) * 4u;
            cp16(kb + off, &kg[idx]);
            cp16(vb + off, &vg[idx]);
        }
        cp_commit();
    };

    {
        const float4* Qg = reinterpret_cast<const float4*>(Q + ((size_t)bh * P_ + p0) * D_);
        #pragma unroll
        for (int c = 0; c < 4; c++) {
            int idx = tid + c * 256;
            int p = idx >> 4, d4 = idx & 15;
            cp16(smem32 + (uint32_t)(p * AT_LD + d4 * 4) * 4u, &Qg[idx]);
        }
    }
    issue_kv(0);

    float m_run[4], l_run[4];
    #pragma unroll
    for (int i = 0; i < 4; i++) { m_run[i] = -1e30f; l_run[i] = 0.0f; }

    double acc[4][2];
    #pragma unroll
    for (int i = 0; i < 4; i++) { acc[i][0] = 0.0; acc[i][1] = 0.0; }

    const int* mbase = mask + ((size_t)b * P_ + p0) * S_;

    for (int st = 0; st < 16; st++) {
        int mk[4][4];
        #pragma unroll
        for (int i = 0; i < 4; i++)
            #pragma unroll
            for (int j = 0; j < 4; j++)
                mk[i][j] = mbase[(size_t)(ty * 4 + i) * S_ + st * 64 + tx + 16 * j];

        cp_wait<0>();
        __syncthreads();
        if (st + 1 < 16) issue_kv(st + 1);

        const float* Kc = Ks0 + (st & 1) * AT_TF;
        const float* Vc = Vs0 + (st & 1) * AT_TF;

        double sacc[4][4];
        #pragma unroll
        for (int i = 0; i < 4; i++)
            #pragma unroll
            for (int j = 0; j < 4; j++) sacc[i][j] = 0.0;

        #pragma unroll
        for (int d4 = 0; d4 < 16; d4++) {
            double2 bk[4];
            #pragma unroll
            for (int j = 0; j < 4; j++)
                bk[j] = *reinterpret_cast<const double2*>(&Kc[(tx + 16 * j) * AT_LD + d4 * 4]);
            #pragma unroll
            for (int i = 0; i < 4; i++) {
                double2 a = *reinterpret_cast<const double2*>(&Qs[(ty * 4 + i) * AT_LD + d4 * 4]);
                #pragma unroll
                for (int j = 0; j < 4; j++) {
                    fma2(sacc[i][j], a.x, bk[j].x);
                    fma2(sacc[i][j], a.y, bk[j].y);
                }
            }
        }

        float sc[4][4];
        #pragma unroll
        for (int i = 0; i < 4; i++)
            #pragma unroll
            for (int j = 0; j < 4; j++) {
                float2 f = unpack2(sacc[i][j]);
                float v = (f.x + f.y) * scale;
                sc[i][j] = mk[i][j] ? -1e30f : v;
            }

        float corr[4];
        #pragma unroll
        for (int i = 0; i < 4; i++) {
            float mx = fmaxf(fmaxf(sc[i][0], sc[i][1]), fmaxf(sc[i][2], sc[i][3]));
            #pragma unroll
            for (int o = 8; o >= 1; o >>= 1)
                mx = fmaxf(mx, __shfl_xor_sync(0xffffffffu, mx, o, 16));
            float mn = fmaxf(m_run[i], mx);
            corr[i] = __expf(m_run[i] - mn);
            float rs = 0.0f;
            #pragma unroll
            for (int j = 0; j < 4; j++) {
                float e = __expf(sc[i][j] - mn);
                sc[i][j] = e;
                rs += e;
            }
            #pragma unroll
            for (int o = 8; o >= 1; o >>= 1)
                rs += __shfl_xor_sync(0xffffffffu, rs, o, 16);
            m_run[i] = mn;
            l_run[i] = l_run[i] * corr[i] + rs;
            #pragma unroll
            for (int j = 0; j < 4; j++)
                Ps[(ty * 4 + i) * AT_LD + tx + 16 * j] = sc[i][j];
        }
        __syncwarp(0xffffffffu);

        #pragma unroll
        for (int i = 0; i < 4; i++) {
            double cc = pack2(corr[i], corr[i]);
            mul2(acc[i][0], cc);
            mul2(acc[i][1], cc);
        }
        #pragma unroll 4
        for (int s4 = 0; s4 < 16; s4++) {
            double2 vv[4];
            #pragma unroll
            for (int k = 0; k < 4; k++)
                vv[k] = *reinterpret_cast<const double2*>(&Vc[(s4 * 4 + k) * AT_LD + tx * 4]);
            #pragma unroll
            for (int i = 0; i < 4; i++) {
                float4 pv = *reinterpret_cast<const float4*>(&Ps[(ty * 4 + i) * AT_LD + s4 * 4]);
                double p0q = pack2(pv.x, pv.x);
                fma2(acc[i][0], p0q, vv[0].x); fma2(acc[i][1], p0q, vv[0].y);
                double p1q = pack2(pv.y, pv.y);
                fma2(acc[i][0], p1q, vv[1].x); fma2(acc[i][1], p1q, vv[1].y);
                double p2q = pack2(pv.z, pv.z);
                fma2(acc[i][0], p2q, vv[2].x); fma2(acc[i][1], p2q, vv[2].y);
                double p3q = pack2(pv.w, pv.w);
                fma2(acc[i][0], p3q, vv[3].x); fma2(acc[i][1], p3q, vv[3].y);
            }
        }
    }

    #pragma unroll
    for (int i = 0; i < 4; i++) {
        int row = ty * 4 + i;
        float inv = 1.0f / l_run[i];
        float2 a0 = unpack2(acc[i][0]);
        float2 a1 = unpack2(acc[i][1]);
        float4 o = make_float4(a0.x * inv, a0.y * inv, a1.x * inv, a1.y * inv);
        *reinterpret_cast<float4*>(
            &ctx[((size_t)b * P_ + p0 + row) * E_ + h * D_ + tx * 4]) = o;
    }
}

// =====================================================================
// launch
// =====================================================================
extern "C" void kernel_launch(void* const* d_in, const int* in_sizes, int n_in,
                              void* d_out, int out_size)
{
    const float* query = (const float*)d_in[0];
    const float* key   = (const float*)d_in[1];
    const float* value = (const float*)d_in[2];
    const int*   maskp = (const int*)  d_in[3];
    const float* Wq    = (const float*)d_in[4];
    const float* Wk    = (const float*)d_in[5];
    const float* Wv    = (const float*)d_in[6];
    const float* Wo    = (const float*)d_in[7];
    const float* bo    = (const float*)d_in[8];
    float* out = (float*)d_out;

    float *dQ, *dK, *dV, *dC;
    cudaGetSymbolAddress((void**)&dQ, g_Q);
    cudaGetSymbolAddress((void**)&dK, g_K);
    cudaGetSymbolAddress((void**)&dV, g_V);
    cudaGetSymbolAddress((void**)&dC, g_ctx);

    cudaFuncSetAttribute(attn_kernel,   cudaFuncAttributeMaxDynamicSharedMemorySize, AT_SMEM_BYTES);
    cudaFuncSetAttribute(mm_qkv_kernel, cudaFuncAttributeMaxDynamicSharedMemorySize, MM_SMEM);
    cudaFuncSetAttribute(mm_out_kernel, cudaFuncAttributeMaxDynamicSharedMemorySize, MM_SMEM);

    dim3 blk(256);
    // Q + K + V projections: mma.sync bf16x3-split, one fused launch
    mm_qkv_kernel<<<dim3(4, 640), blk, MM_SMEM>>>(query, Wq, dQ, key, Wk, dK, value, Wv, dV);
    // fused masked attention (fp32, f32x2)
    attn_kernel<<<dim3(B_ * H_, P_ / 64), blk, AT_SMEM_BYTES>>>(dQ, dK, dV, maskp, dC);
    // output projection + bias: mma.sync bf16x3-split
    mm_out_kernel<<<dim3(4, 128), blk, MM_SMEM>>>(dC, Wo, bo, out);
}

// round 17
// speedup vs baseline: 1.9590x; 1.2670x over previous
#include <cuda_runtime.h>
#include <cuda_fp16.h>
#include <cstdint>
#include <cstddef>

// Problem constants
#define B_  32
#define P_  512
#define S_  1024
#define E_  512
#define H_  8
#define D_  64

// Scratch (allocation-free rule: __device__ globals)
__device__ float g_Q[(size_t)B_ * H_ * P_ * D_];   // (B,H,P,D)
__device__ float g_K[(size_t)B_ * H_ * S_ * D_];   // (B,H,S,D)
__device__ float g_V[(size_t)B_ * H_ * S_ * D_];   // (B,H,S,D)
__device__ float g_ctx[(size_t)B_ * P_ * E_];      // (B,P,E)

// ---------------- mma.sync plumbing (hardware-verified in round 16) ----------
__device__ __forceinline__ void ldm_x4(uint32_t* r, uint32_t addr) {
    asm volatile("ldmatrix.sync.aligned.m8n8.x4.shared.b16 {%0,%1,%2,%3}, [%4];"
                 : "=r"(r[0]), "=r"(r[1]), "=r"(r[2]), "=r"(r[3]) : "r"(addr));
}
__device__ __forceinline__ void mma_bf16(float* d, const uint32_t* a, const uint32_t* b) {
    asm volatile(
        "mma.sync.aligned.m16n8k16.row.col.f32.bf16.bf16.f32 "
        "{%0,%1,%2,%3}, {%4,%5,%6,%7}, {%8,%9}, {%0,%1,%2,%3};"
        : "+f"(d[0]), "+f"(d[1]), "+f"(d[2]), "+f"(d[3])
        : "r"(a[0]), "r"(a[1]), "r"(a[2]), "r"(a[3]), "r"(b[0]), "r"(b[1]));
}
__device__ __forceinline__ void mma_f16(float* d, const uint32_t* a, const uint32_t* b) {
    asm volatile(
        "mma.sync.aligned.m16n8k16.row.col.f32.f16.f16.f32 "
        "{%0,%1,%2,%3}, {%4,%5,%6,%7}, {%8,%9}, {%0,%1,%2,%3};"
        : "+f"(d[0]), "+f"(d[1]), "+f"(d[2]), "+f"(d[3])
        : "r"(a[0]), "r"(a[1]), "r"(a[2]), "r"(a[3]), "r"(b[0]), "r"(b[1]));
}

// bf16x2 / f16x2 pack helpers (d = {hi:upper, lo:lower})
__device__ __forceinline__ uint32_t bf2(float lo, float hi) {
    uint32_t r; asm("cvt.rn.bf16x2.f32 %0, %1, %2;" : "=r"(r) : "f"(hi), "f"(lo)); return r;
}
__device__ __forceinline__ float2 bf2f(uint32_t p) {
    return make_float2(__uint_as_float(p << 16), __uint_as_float(p & 0xffff0000u));
}
__device__ __forceinline__ uint32_t fh2(float lo, float hi) {
    uint32_t r; asm("cvt.rn.f16x2.f32 %0, %1, %2;" : "=r"(r) : "f"(hi), "f"(lo)); return r;
}

// =====================================================================
// Tensor-core split-precision GEMM via mma.sync (MEASURED: 328us/906 prior,
// tensor=64.8%, rel_err 1.1e-5). FROZEN this round.
// =====================================================================
#define MM_LDB  144
#define MM_TILE (128 * MM_LDB)
#define MM_AH   0
#define MM_AL   (MM_TILE)
#define MM_BH   (2 * MM_TILE)
#define MM_BL   (3 * MM_TILE)
#define MM_SMEM (4 * MM_TILE)             // 73728 B

__device__ __forceinline__
void split_store2(char* smem, int baseH, int baseL, uint32_t off, float4 v) {
    uint32_t h0 = bf2(v.x, v.y); float2 f0 = bf2f(h0);
    uint32_t h1 = bf2(v.z, v.w); float2 f1 = bf2f(h1);
    uint32_t l0 = bf2(v.x - f0.x, v.y - f0.y);
    uint32_t l1 = bf2(v.z - f1.x, v.w - f1.y);
    *reinterpret_cast<uint2*>(smem + baseH + off) = make_uint2(h0, h1);
    *reinterpret_cast<uint2*>(smem + baseL + off) = make_uint2(l0, l1);
}

__device__ __forceinline__
void mm_gemm_body(char* smem, const float* __restrict__ A, const float* __restrict__ W,
                  const float* __restrict__ bias, float* __restrict__ out,
                  int m0, int seq_lg, int mode)
{
    const int tid    = threadIdx.x;
    const int lane   = tid & 31;
    const int wid    = tid >> 5;
    const int warp_m = wid & 3;
    const int warp_n = wid >> 2;
    const int n0 = blockIdx.x * 128;
    const uint32_t smem32 = (uint32_t)__cvta_generic_to_shared(smem);

    const float4* Ag = reinterpret_cast<const float4*>(A);
    const float4* Wg = reinterpret_cast<const float4*>(W);

    float d[2][8][4];
    #pragma unroll
    for (int mt = 0; mt < 2; mt++)
        #pragma unroll
        for (int nt = 0; nt < 8; nt++)
            #pragma unroll
            for (int r = 0; r < 4; r++) d[mt][nt][r] = 0.0f;

    const int a_row_off = lane & 15;
    const int a_col_off = (lane >> 4) * 16;
    const int b_row_off = ((lane >> 4) << 3) + (lane & 7);
    const int b_col_off = ((lane >> 3) & 1) * 16;

    for (int chunk = 0; chunk < 8; chunk++) {
        __syncthreads();
        #pragma unroll
        for (int c = 0; c < 8; c++) {
            int idx = tid + c * 256;
            int row = idx >> 4, f4 = idx & 15;
            float4 v = Ag[(size_t)(m0 + row) * 128 + chunk * 16 + f4];
            split_store2(smem, MM_AH, MM_AL, (uint32_t)(row * MM_LDB + f4 * 8), v);
        }
        #pragma unroll
        for (int c = 0; c < 8; c++) {
            int idx = tid + c * 256;
            int row = idx >> 4, f4 = idx & 15;
            float4 v = Wg[(size_t)(n0 + row) * 128 + chunk * 16 + f4];
            split_store2(smem, MM_BH, MM_BL, (uint32_t)(row * MM_LDB + f4 * 8), v);
        }
        __syncthreads();

        #pragma unroll
        for (int ks = 0; ks < 4; ks++) {
            const int kb = ks * 32;
            uint32_t ah[2][4];
            #pragma unroll
            for (int mt = 0; mt < 2; mt++)
                ldm_x4(ah[mt], smem32 + MM_AH +
                       (uint32_t)((warp_m * 32 + mt * 16 + a_row_off) * MM_LDB + a_col_off + kb));
            uint32_t bh[4][4];
            #pragma unroll
            for (int p = 0; p < 4; p++)
                ldm_x4(bh[p], smem32 + MM_BH +
                       (uint32_t)((warp_n * 64 + p * 16 + b_row_off) * MM_LDB + b_col_off + kb));
            #pragma unroll
            for (int mt = 0; mt < 2; mt++)
                #pragma unroll
                for (int nt = 0; nt < 8; nt++)
                    mma_bf16(d[mt][nt], ah[mt], &bh[nt >> 1][(nt & 1) * 2]);
            {
                uint32_t bl[4][4];
                #pragma unroll
                for (int p = 0; p < 4; p++)
                    ldm_x4(bl[p], smem32 + MM_BL +
                           (uint32_t)((warp_n * 64 + p * 16 + b_row_off) * MM_LDB + b_col_off + kb));
                #pragma unroll
                for (int mt = 0; mt < 2; mt++)
                    #pragma unroll
                    for (int nt = 0; nt < 8; nt++)
                        mma_bf16(d[mt][nt], ah[mt], &bl[nt >> 1][(nt & 1) * 2]);
            }
            {
                uint32_t al[2][4];
                #pragma unroll
                for (int mt = 0; mt < 2; mt++)
                    ldm_x4(al[mt], smem32 + MM_AL +
                           (uint32_t)((warp_m * 32 + mt * 16 + a_row_off) * MM_LDB + a_col_off + kb));
                #pragma unroll
                for (int mt = 0; mt < 2; mt++)
                    #pragma unroll
                    for (int nt = 0; nt < 8; nt++)
                        mma_bf16(d[mt][nt], al[mt], &bh[nt >> 1][(nt & 1) * 2]);
            }
        }
    }

    const int gid = lane >> 2, tig = lane & 3;
    const int seq_mask = (1 << seq_lg) - 1;
    #pragma unroll
    for (int mt = 0; mt < 2; mt++) {
        #pragma unroll
        for (int half = 0; half < 2; half++) {
            int m = m0 + warp_m * 32 + mt * 16 + gid + half * 8;
            #pragma unroll
            for (int nt = 0; nt < 8; nt++) {
                int n = n0 + warp_n * 64 + nt * 8 + tig * 2;
                float2 v = make_float2(d[mt][nt][half * 2], d[mt][nt][half * 2 + 1]);
                if (mode == 0) {
                    v.x += bias[n]; v.y += bias[n + 1];
                    *reinterpret_cast<float2*>(&out[(size_t)m * E_ + n]) = v;
                } else {
                    int bb = m >> seq_lg, sq = m & seq_mask;
                    int hh = n >> 6, dd = n & 63;
                    *reinterpret_cast<float2*>(
                        &out[(size_t)(((bb * H_ + hh) << seq_lg) | sq) * 64 + dd]) = v;
                }
            }
        }
    }
}

__global__ __launch_bounds__(256, 2)
void mm_qkv_kernel(const float* __restrict__ Qin, const float* __restrict__ Wq, float* __restrict__ outQ,
                   const float* __restrict__ Kin, const float* __restrict__ Wk, float* __restrict__ outK,
                   const float* __restrict__ Vin, const float* __restrict__ Wv, float* __restrict__ outV)
{
    extern __shared__ char mmsm[];
    const int y = blockIdx.y;
    if (y < 128)      mm_gemm_body(mmsm, Qin, Wq, nullptr, outQ, y * 128, 9, 1);
    else if (y < 384) mm_gemm_body(mmsm, Kin, Wk, nullptr, outK, (y - 128) * 128, 10, 1);
    else              mm_gemm_body(mmsm, Vin, Wv, nullptr, outV, (y - 384) * 128, 10, 1);
}

__global__ __launch_bounds__(256, 2)
void mm_out_kernel(const float* __restrict__ A, const float* __restrict__ Wo,
                   const float* __restrict__ bo, float* __restrict__ out)
{
    extern __shared__ char mmsm2[];
    mm_gemm_body(mmsm2, A, Wo, bo, out, blockIdx.y * 128, 9, 0);
}

// =====================================================================
// Fused masked attention via mma.sync.
// Grid (B*H, P/64), 128 threads (4 warps). Warp w owns p-rows [16w,16w+16).
// Scores: S = (Q*0.125)K^T, bf16x3 (Q pre-scaled then split; exponent err ~1e-5).
// Softmax in D-fragments (row=lane>>2/+8, cols 2(lane&3)+8nt — verified map);
// row reduce = shfl over the 4-lane quad. Probs -> fp16 -> smem (warp-private
// rows => __syncwarp only). Ctx: P(fp16) x V(fp16 2-split vh+vl), V transposed
// in smem so B operand reuses the verified non-trans [n][k] ldmatrix pattern.
// Predicted ctx rel err ~5e-4 (P fp16 rounding dominant) < 1e-3 budget.
// =====================================================================
#define FA_LDB  144
#define FA_T    (64 * FA_LDB)             // 9216 B per 64x64 b16 tile
#define FA_QH   0
#define FA_QL   (FA_T)
#define FA_KH   (2 * FA_T)
#define FA_KL   (3 * FA_T)
#define FA_VH   (4 * FA_T)                // Vt hi fp16, [d][s]
#define FA_VL   (5 * FA_T)                // Vt lo fp16
#define FA_PH   (6 * FA_T)                // probs fp16, [p][s]
#define FA_SMEM (7 * FA_T)                // 64512 B

__global__ __launch_bounds__(128)
void attn_mma_kernel(const float* __restrict__ Q, const float* __restrict__ K,
                     const float* __restrict__ V, const int* __restrict__ mask,
                     float* __restrict__ ctx)
{
    extern __shared__ char fsm[];
    const int tid  = threadIdx.x;
    const int lane = tid & 31;
    const int w    = tid >> 5;
    const int bh   = blockIdx.x;
    const int b    = bh >> 3;
    const int h    = bh & 7;
    const int p0   = blockIdx.y * 64;
    const uint32_t smem32 = (uint32_t)__cvta_generic_to_shared(fsm);

    const float4* Qg = reinterpret_cast<const float4*>(Q + ((size_t)bh * P_ + p0) * D_);
    const float4* Kg = reinterpret_cast<const float4*>(K + (size_t)bh * S_ * D_);
    const float4* Vg = reinterpret_cast<const float4*>(V + (size_t)bh * S_ * D_);

    // ---- prologue: Q tile, pre-scaled by 1/8, split bf16 ----
    #pragma unroll
    for (int c = 0; c < 8; c++) {
        int idx = tid + c * 128;
        int row = idx >> 4, f4 = idx & 15;
        float4 v = Qg[row * 16 + f4];
        v.x *= 0.125f; v.y *= 0.125f; v.z *= 0.125f; v.w *= 0.125f;
        split_store2(fsm, FA_QH, FA_QL, (uint32_t)(row * FA_LDB + f4 * 8), v);
    }

    const int a_row = lane & 15, a_col = (lane >> 4) * 16;
    const int b_row = ((lane >> 4) << 3) + (lane & 7), b_col = ((lane >> 3) & 1) * 16;
    const int r0 = lane >> 2;          // D-fragment row (0..7); +8 for second half
    const int cq = lane & 3;           // D-fragment col pair index

    float m_run[2] = {-1e30f, -1e30f};
    float l_run[2] = {0.0f, 0.0f};
    float dacc[8][4];
    #pragma unroll
    for (int nt = 0; nt < 8; nt++)
        #pragma unroll
        for (int r = 0; r < 4; r++) dacc[nt][r] = 0.0f;

    const int* mrow0 = mask + ((size_t)b * P_ + p0 + 16 * w + r0) * S_;
    const int* mrow1 = mrow0 + 8 * (size_t)S_;

    for (int st = 0; st < 16; st++) {
        __syncthreads();   // all warps' ldmatrix reads of prior K/V tiles done

        // ---- convert K (split bf16) and V (transpose + fp16 2-split) ----
        #pragma unroll
        for (int c = 0; c < 8; c++) {
            int idx = tid + c * 128;
            int row = idx >> 4, f4 = idx & 15;
            float4 kv = Kg[st * 1024 + row * 16 + f4];
            split_store2(fsm, FA_KH, FA_KL, (uint32_t)(row * FA_LDB + f4 * 8), kv);
            float4 vv = Vg[st * 1024 + row * 16 + f4];
            float vj[4] = {vv.x, vv.y, vv.z, vv.w};
            #pragma unroll
            for (int j = 0; j < 4; j++) {
                __half hv = __float2half_rn(vj[j]);
                __half lv = __float2half_rn(vj[j] - __half2float(hv));
                *reinterpret_cast<__half*>(fsm + FA_VH + (f4 * 4 + j) * FA_LDB + row * 2) = hv;
                *reinterpret_cast<__half*>(fsm + FA_VL + (f4 * 4 + j) * FA_LDB + row * 2) = lv;
            }
        }
        __syncthreads();

        // ---- scores: bf16x3 Q.K^T ----
        float sacc[8][4];
        #pragma unroll
        for (int nt = 0; nt < 8; nt++)
            #pragma unroll
            for (int r = 0; r < 4; r++) sacc[nt][r] = 0.0f;

        #pragma unroll
        for (int ks = 0; ks < 4; ks++) {
            const int kb = ks * 32;
            uint32_t qh[4], ql[4];
            ldm_x4(qh, smem32 + FA_QH + (uint32_t)((16 * w + a_row) * FA_LDB + a_col + kb));
            ldm_x4(ql, smem32 + FA_QL + (uint32_t)((16 * w + a_row) * FA_LDB + a_col + kb));
            uint32_t kh[4][4];
            #pragma unroll
            for (int p = 0; p < 4; p++)
                ldm_x4(kh[p], smem32 + FA_KH + (uint32_t)((p * 16 + b_row) * FA_LDB + b_col + kb));
            #pragma unroll
            for (int nt = 0; nt < 8; nt++)
                mma_bf16(sacc[nt], qh, &kh[nt >> 1][(nt & 1) * 2]);
            {
                uint32_t kl[4][4];
                #pragma unroll
                for (int p = 0; p < 4; p++)
                    ldm_x4(kl[p], smem32 + FA_KL + (uint32_t)((p * 16 + b_row) * FA_LDB + b_col + kb));
                #pragma unroll
                for (int nt = 0; nt < 8; nt++)
                    mma_bf16(sacc[nt], qh, &kl[nt >> 1][(nt & 1) * 2]);
            }
            #pragma unroll
            for (int nt = 0; nt < 8; nt++)
                mma_bf16(sacc[nt], ql, &kh[nt >> 1][(nt & 1) * 2]);
        }

        // ---- mask (int32: nonzero => masked) ----
        const int* m0p = mrow0 + st * 64;
        const int* m1p = mrow1 + st * 64;
        #pragma unroll
        for (int nt = 0; nt < 8; nt++) {
            int s0 = nt * 8 + 2 * cq;
            if (m0p[s0])     sacc[nt][0] = -1e30f;
            if (m0p[s0 + 1]) sacc[nt][1] = -1e30f;
            if (m1p[s0])     sacc[nt][2] = -1e30f;
            if (m1p[s0 + 1]) sacc[nt][3] = -1e30f;
        }

        // ---- online softmax in fragments ----
        float mx0 = -1e30f, mx1 = -1e30f;
        #pragma unroll
        for (int nt = 0; nt < 8; nt++) {
            mx0 = fmaxf(mx0, fmaxf(sacc[nt][0], sacc[nt][1]));
            mx1 = fmaxf(mx1, fmaxf(sacc[nt][2], sacc[nt][3]));
        }
        mx0 = fmaxf(mx0, __shfl_xor_sync(0xffffffffu, mx0, 1, 4));
        mx0 = fmaxf(mx0, __shfl_xor_sync(0xffffffffu, mx0, 2, 4));
        mx1 = fmaxf(mx1, __shfl_xor_sync(0xffffffffu, mx1, 1, 4));
        mx1 = fmaxf(mx1, __shfl_xor_sync(0xffffffffu, mx1, 2, 4));
        float mn0 = fmaxf(m_run[0], mx0), mn1 = fmaxf(m_run[1], mx1);
        float c0 = __expf(m_run[0] - mn0), c1 = __expf(m_run[1] - mn1);
        float rs0 = 0.0f, rs1 = 0.0f;
        #pragma unroll
        for (int nt = 0; nt < 8; nt++) {
            float e0 = __expf(sacc[nt][0] - mn0);
            float e1 = __expf(sacc[nt][1] - mn0);
            float e2 = __expf(sacc[nt][2] - mn1);
            float e3 = __expf(sacc[nt][3] - mn1);
            rs0 += e0 + e1; rs1 += e2 + e3;
            int sc2 = (nt * 8 + 2 * cq) * 2;
            *reinterpret_cast<uint32_t*>(fsm + FA_PH + (16 * w + r0) * FA_LDB + sc2)     = fh2(e0, e1);
            *reinterpret_cast<uint32_t*>(fsm + FA_PH + (16 * w + r0 + 8) * FA_LDB + sc2) = fh2(e2, e3);
        }
        rs0 += __shfl_xor_sync(0xffffffffu, rs0, 1, 4);
        rs0 += __shfl_xor_sync(0xffffffffu, rs0, 2, 4);
        rs1 += __shfl_xor_sync(0xffffffffu, rs1, 1, 4);
        rs1 += __shfl_xor_sync(0xffffffffu, rs1, 2, 4);
        m_run[0] = mn0; m_run[1] = mn1;
        l_run[0] = l_run[0] * c0 + rs0;
        l_run[1] = l_run[1] * c1 + rs1;

        #pragma unroll
        for (int nt = 0; nt < 8; nt++) {
            dacc[nt][0] *= c0; dacc[nt][1] *= c0;
            dacc[nt][2] *= c1; dacc[nt][3] *= c1;
        }
        __syncwarp();   // Ph rows are warp-private: warp-local ordering suffices

        // ---- ctx: P(fp16) x Vt(fp16 hi+lo) ----
        #pragma unroll
        for (int ks = 0; ks < 4; ks++) {
            const int kb = ks * 32;
            uint32_t pf[4];
            ldm_x4(pf, smem32 + FA_PH + (uint32_t)((16 * w + a_row) * FA_LDB + a_col + kb));
            uint32_t vh[4][4];
            #pragma unroll
            for (int p = 0; p < 4; p++)
                ldm_x4(vh[p], smem32 + FA_VH + (uint32_t)((p * 16 + b_row) * FA_LDB + b_col + kb));
            #pragma unroll
            for (int nt = 0; nt < 8; nt++)
                mma_f16(dacc[nt], pf, &vh[nt >> 1][(nt & 1) * 2]);
            {
                uint32_t vl[4][4];
                #pragma unroll
                for (int p = 0; p < 4; p++)
                    ldm_x4(vl[p], smem32 + FA_VL + (uint32_t)((p * 16 + b_row) * FA_LDB + b_col + kb));
                #pragma unroll
                for (int nt = 0; nt < 8; nt++)
                    mma_f16(dacc[nt], pf, &vl[nt >> 1][(nt & 1) * 2]);
            }
        }
    }

    // ---- epilogue: normalize and write ctx ----
    float i0 = 1.0f / l_run[0], i1 = 1.0f / l_run[1];
    size_t ro0 = ((size_t)b * P_ + p0 + 16 * w + r0) * E_ + h * 64;
    size_t ro1 = ro0 + 8 * (size_t)E_;
    #pragma unroll
    for (int nt = 0; nt < 8; nt++) {
        int col = nt * 8 + 2 * cq;
        *reinterpret_cast<float2*>(&ctx[ro0 + col]) =
            make_float2(dacc[nt][0] * i0, dacc[nt][1] * i0);
        *reinterpret_cast<float2*>(&ctx[ro1 + col]) =
            make_float2(dacc[nt][2] * i1, dacc[nt][3] * i1);
    }
}

// =====================================================================
// launch
// =====================================================================
extern "C" void kernel_launch(void* const* d_in, const int* in_sizes, int n_in,
                              void* d_out, int out_size)
{
    const float* query = (const float*)d_in[0];
    const float* key   = (const float*)d_in[1];
    const float* value = (const float*)d_in[2];
    const int*   maskp = (const int*)  d_in[3];
    const float* Wq    = (const float*)d_in[4];
    const float* Wk    = (const float*)d_in[5];
    const float* Wv    = (const float*)d_in[6];
    const float* Wo    = (const float*)d_in[7];
    const float* bo    = (const float*)d_in[8];
    float* out = (float*)d_out;

    float *dQ, *dK, *dV, *dC;
    cudaGetSymbolAddress((void**)&dQ, g_Q);
    cudaGetSymbolAddress((void**)&dK, g_K);
    cudaGetSymbolAddress((void**)&dV, g_V);
    cudaGetSymbolAddress((void**)&dC, g_ctx);

    cudaFuncSetAttribute(mm_qkv_kernel,   cudaFuncAttributeMaxDynamicSharedMemorySize, MM_SMEM);
    cudaFuncSetAttribute(mm_out_kernel,   cudaFuncAttributeMaxDynamicSharedMemorySize, MM_SMEM);
    cudaFuncSetAttribute(attn_mma_kernel, cudaFuncAttributeMaxDynamicSharedMemorySize, FA_SMEM);

    // Q + K + V projections: mma.sync bf16x3-split, one fused launch
    mm_qkv_kernel<<<dim3(4, 640), dim3(256), MM_SMEM>>>(query, Wq, dQ, key, Wk, dK, value, Wv, dV);
    // fused masked attention: mma.sync (scores bf16x3, ctx fp16 V-split)
    attn_mma_kernel<<<dim3(B_ * H_, P_ / 64), dim3(128), FA_SMEM>>>(dQ, dK, dV, maskp, dC);
    // output projection + bias: mma.sync bf16x3-split
    mm_out_kernel<<<dim3(4, 128), dim3(256), MM_SMEM>>>(dC, Wo, bo, out);
}